// round 15
// baseline (speedup 1.0000x reference)
#include <cuda_runtime.h>
#include <cstdint>

#define DD 192
#define LL 1024
#define BT 128
#define NS 8
#define ROWS_S   (BT*NS)   /* 1024 */
#define NPART 4
#define NB_TAIL 128
#define NB_FRONT 96

typedef unsigned long long ull;

// ---------------- scratch (device globals; no allocs allowed) ----------------
__device__ float g_qt  [ROWS_S * DD];
__device__ float g_wkq [DD * DD];
__device__ float g_wvo [DD * DD];
__device__ float g_y   [NPART * ROWS_S * DD];
__device__ float g_den [NPART * ROWS_S];
__device__ float g_t1  [ROWS_S * DD];
__device__ float g_t2  [ROWS_S * DD];
__device__ float g_qkvb[ROWS_S * 576];
__device__ float g_hid [ROWS_S * 512];
__device__ int   g_bar = 0;
__device__ int   g_gen = 0;

// ---------------- packed f32x2 helpers ----------------
__device__ __forceinline__ ull dup2(float x) {
  ull r; asm("mov.b64 %0, {%1, %1};" : "=l"(r) : "f"(x)); return r;
}
__device__ __forceinline__ ull pack2(float lo, float hi) {
  ull r; asm("mov.b64 %0, {%1, %2};" : "=l"(r) : "f"(lo), "f"(hi)); return r;
}
__device__ __forceinline__ void unpack2(ull v, float& lo, float& hi) {
  asm("mov.b64 {%0, %1}, %2;" : "=f"(lo), "=f"(hi) : "l"(v));
}
__device__ __forceinline__ void ffma2(ull& d, ull a, ull b) {
  asm("fma.rn.f32x2 %0, %1, %2, %0;" : "+l"(d) : "l"(a), "l"(b));
}
__device__ __forceinline__ ull add2(ull a, ull b) {
  ull r; asm("add.rn.f32x2 %0, %1, %2;" : "=l"(r) : "l"(a), "l"(b)); return r;
}
__device__ __forceinline__ ull mul2(ull a, ull b) {
  ull r; asm("mul.rn.f32x2 %0, %1, %2;" : "=l"(r) : "l"(a), "l"(b)); return r;
}

// ---------------- grid-wide barrier (all CTAs resident by construction) ----------------
__device__ __forceinline__ void grid_sync(int nb) {
  __syncthreads();
  if (threadIdx.x == 0) {
    volatile int* genp = &g_gen;
    int gen = *genp;
    __threadfence();
    if (atomicAdd(&g_bar, 1) == nb - 1) {
      g_bar = 0;
      __threadfence();
      *genp = gen + 1;
    } else {
      while (*genp == gen) { }
    }
  }
  __syncthreads();
}

// ---------------- smem layouts ----------------
struct SmLn { float Af[32][193]; __align__(16) float Ws[2][16][68]; float gs[DD], bs[DD]; };
struct SmGs { __align__(16) float As[2][16][36]; __align__(16) float Ws[2][16][68]; };
struct SmMM { __align__(16) float As[16][34]; __align__(16) float Ws[16][68]; };
#define SM_FRONT_BYTES (sizeof(SmLn) > sizeof(SmMM) ? sizeof(SmLn) : sizeof(SmMM))
#define SM_MHA_BYTES ((64*48 + 2*128*48 + 64*128)*4)

// ---------------- device fn: 192x192 matmul tile (z=0: wk^T@wq, z=1: wo@wv) ----------------
__device__ void dev_mm192(char* smraw,
                          const float* __restrict__ A, const float* __restrict__ B,
                          float* __restrict__ C, int transA, int tm, int tn) {
  SmMM* sm = (SmMM*)smraw;
  int t = threadIdx.x;
  int m0 = tm * 32, n0 = tn * 64;
  int ty = t >> 4, tx = t & 15;
  ull acc[4] = {};
  int wn = t >> 2, wk2 = (t & 3) << 2;
  for (int k0 = 0; k0 < DD; k0 += 16) {
    float av[2]; int ak[2], am[2];
#pragma unroll
    for (int h = 0; h < 2; h++) {
      int i = t + h*256;
      ak[h] = i >> 5; am[h] = i & 31;
      av[h] = transA ? A[(size_t)(k0 + ak[h])*DD + m0 + am[h]]
                     : A[(size_t)(m0 + am[h])*DD + k0 + ak[h]];
    }
    float wv4[4];
#pragma unroll
    for (int j = 0; j < 4; j++) wv4[j] = B[(size_t)(k0 + wk2 + j)*DD + n0 + wn];
    __syncthreads();
#pragma unroll
    for (int h = 0; h < 2; h++) sm->As[ak[h]][am[h]] = av[h];
#pragma unroll
    for (int j = 0; j < 4; j++) sm->Ws[wk2 + j][wn] = wv4[j];
    __syncthreads();
#pragma unroll
    for (int k = 0; k < 16; k++) {
      ull ap = *(const ull*)&sm->As[k][ty*2];
      float4 w4 = *(const float4*)&sm->Ws[k][tx*4];
      ffma2(acc[0], ap, dup2(w4.x));
      ffma2(acc[1], ap, dup2(w4.y));
      ffma2(acc[2], ap, dup2(w4.z));
      ffma2(acc[3], ap, dup2(w4.w));
    }
  }
  int m = m0 + ty*2, n = n0 + tx*4;
  float r0[4], r1[4];
#pragma unroll
  for (int j = 0; j < 4; j++) unpack2(acc[j], r0[j], r1[j]);
  *(float4*)(C + (size_t)m*DD + n)     = make_float4(r0[0], r0[1], r0[2], r0[3]);
  *(float4*)(C + (size_t)(m+1)*DD + n) = make_float4(r1[0], r1[1], r1[2], r1[3]);
  __syncthreads();
}

// ---------------- device fn: fused LN + GEMM tile (K=192) ----------------
__device__ void dev_gemm_ln(char* smraw,
                            const float* __restrict__ A, const float* __restrict__ W,
                            const float* __restrict__ bias,
                            const float* __restrict__ gamma, const float* __restrict__ beta,
                            float* __restrict__ C, int ldc, float alpha, int relu, int perm,
                            int tm, int tn) {
  SmLn* sm = (SmLn*)smraw;
  int t = threadIdx.x;
  int m0 = tm * 32, n0 = tn * 64;
  int lw = t >> 2, lk = (t & 3) << 2;
  const float* Wp = W + (size_t)(n0 + lw)*DD + lk;
  float4 w_reg[2];
  w_reg[0] = *(const float4*)(Wp + 0);
  w_reg[1] = *(const float4*)(Wp + 16);
  for (int i = t; i < DD; i += 256) { sm->gs[i] = gamma[i]; sm->bs[i] = beta[i]; }
  for (int i = t; i < 32*DD; i += 256) {
    int r = i / DD, c = i - r*DD;
    int sr = m0 + r;
    if (perm) { int w = sr; int bb = w >> 7, n = (w >> 4) & 7, tt = w & 15; sr = (bb*16 + tt)*8 + n; }
    sm->Af[r][c] = A[(size_t)sr*DD + c];
  }
  __syncthreads();
  int wid = t >> 5, lane = t & 31;
#pragma unroll
  for (int i = 0; i < 4; i++) {
    int r = wid*4 + i;
    float s = 0.f, s2 = 0.f;
#pragma unroll
    for (int c0 = 0; c0 < 6; c0++) { float v = sm->Af[r][c0*32 + lane]; s += v; s2 += v*v; }
#pragma unroll
    for (int o = 16; o; o >>= 1) {
      s  += __shfl_xor_sync(0xffffffffu, s,  o);
      s2 += __shfl_xor_sync(0xffffffffu, s2, o);
    }
    float m = s * (1.f/DD);
    float inv = rsqrtf(fmaxf(s2*(1.f/DD) - m*m, 0.f) + 1e-5f);
#pragma unroll
    for (int c0 = 0; c0 < 6; c0++) {
      int c = c0*32 + lane;
      sm->Af[r][c] = (sm->Af[r][c] - m)*inv*sm->gs[c] + sm->bs[c];
    }
  }
  sm->Ws[0][lk+0][lw] = w_reg[0].x; sm->Ws[0][lk+1][lw] = w_reg[0].y;
  sm->Ws[0][lk+2][lw] = w_reg[0].z; sm->Ws[0][lk+3][lw] = w_reg[0].w;
  __syncthreads();

  int ty = t >> 4, tx = t & 15;
  ull acc[4] = {};
  const int NK = 12;
  for (int i = 0; i < NK; i++) {
    int cur = i & 1;
    if (i + 2 < NK) w_reg[cur] = *(const float4*)(Wp + (i+2)*16);
#pragma unroll
    for (int k = 0; k < 16; k++) {
      ull ap = pack2(sm->Af[ty*2][i*16+k], sm->Af[ty*2+1][i*16+k]);
      float4 w4 = *(const float4*)&sm->Ws[cur][k][tx*4];
      ffma2(acc[0], ap, dup2(w4.x));
      ffma2(acc[1], ap, dup2(w4.y));
      ffma2(acc[2], ap, dup2(w4.z));
      ffma2(acc[3], ap, dup2(w4.w));
    }
    if (i + 1 < NK) {
      int nxt = (i+1) & 1;
      float4 wn4 = w_reg[nxt];
      sm->Ws[nxt][lk+0][lw] = wn4.x; sm->Ws[nxt][lk+1][lw] = wn4.y;
      sm->Ws[nxt][lk+2][lw] = wn4.z; sm->Ws[nxt][lk+3][lw] = wn4.w;
    }
    __syncthreads();
  }
  int m = m0 + ty*2, n = n0 + tx*4;
  float r0[4], r1[4];
#pragma unroll
  for (int j = 0; j < 4; j++) {
    float lo, hi; unpack2(acc[j], lo, hi);
    float bv = bias ? bias[n+j] : 0.f;
    float v0 = lo*alpha + bv;
    float v1 = hi*alpha + bv;
    if (relu) { v0 = fmaxf(v0, 0.f); v1 = fmaxf(v1, 0.f); }
    r0[j] = v0; r1[j] = v1;
  }
  *(float4*)(C + (size_t)m*ldc + n)     = make_float4(r0[0], r0[1], r0[2], r0[3]);
  *(float4*)(C + (size_t)(m+1)*ldc + n) = make_float4(r1[0], r1[1], r1[2], r1[3]);
  __syncthreads();
}

// ---------------- device fn: small-tile GEMM (double-buffered) ----------------
__device__ void dev_gemm_s(char* smraw,
                           const float* __restrict__ A, const float* __restrict__ W,
                           const float* __restrict__ bias, const float* __restrict__ res,
                           const float* __restrict__ rowdiv,
                           float* __restrict__ C, int Ncols, int K, int ldc,
                           float alpha, int relu, int nacc, int tm, int tn) {
  SmGs* sm = (SmGs*)smraw;
  int t = threadIdx.x;
  int m0 = tm * 32, n0 = tn * 64;
  int lrA = t >> 2, lcA = (t & 3) << 2;
  const float* Ap = A + (size_t)(m0 + (lrA & 31)) * K + lcA;
  const float* Wp = W + (size_t)(n0 + lrA) * K + lcA;
  float rsA = 1.f;
  if (rowdiv && t < 128) {
    float d = 0.f;
    for (int p = 0; p < nacc; p++) d += rowdiv[p*ROWS_S + m0 + lrA];
    rsA = 1.f / d;
  }
  int ty = t >> 4, tx = t & 15;
  int NK = K >> 4;
  ull acc[4] = {};
  float4 a_reg[2], w_reg[2];
  auto loadT = [&](int i, float4& a0, float4& w0) {
    a0 = make_float4(0.f,0.f,0.f,0.f);
    if (t < 128) {
      a0 = *(const float4*)(Ap + i*16);
      for (int p = 1; p < nacc; p++) {
        float4 a2 = *(const float4*)(Ap + (size_t)p*ROWS_S*DD + i*16);
        a0.x += a2.x; a0.y += a2.y; a0.z += a2.z; a0.w += a2.w;
      }
      a0.x *= rsA; a0.y *= rsA; a0.z *= rsA; a0.w *= rsA;
    }
    w0 = *(const float4*)(Wp + i*16);
  };
  loadT(0, a_reg[0], w_reg[0]);
  if (NK > 1) loadT(1, a_reg[1], w_reg[1]);
  if (t < 128) {
    sm->As[0][lcA+0][lrA] = a_reg[0].x; sm->As[0][lcA+1][lrA] = a_reg[0].y;
    sm->As[0][lcA+2][lrA] = a_reg[0].z; sm->As[0][lcA+3][lrA] = a_reg[0].w;
  }
  sm->Ws[0][lcA+0][lrA] = w_reg[0].x; sm->Ws[0][lcA+1][lrA] = w_reg[0].y;
  sm->Ws[0][lcA+2][lrA] = w_reg[0].z; sm->Ws[0][lcA+3][lrA] = w_reg[0].w;
  __syncthreads();
  for (int i = 0; i < NK; i++) {
    int cur = i & 1;
    if (i + 2 < NK) loadT(i+2, a_reg[cur], w_reg[cur]);
#pragma unroll
    for (int k = 0; k < 16; k++) {
      ull ap = *(const ull*)&sm->As[cur][k][ty*2];
      float4 wv = *(const float4*)&sm->Ws[cur][k][tx*4];
      ffma2(acc[0], ap, dup2(wv.x));
      ffma2(acc[1], ap, dup2(wv.y));
      ffma2(acc[2], ap, dup2(wv.z));
      ffma2(acc[3], ap, dup2(wv.w));
    }
    if (i + 1 < NK) {
      int nxt = (i+1) & 1;
      float4 an = a_reg[nxt], wn4 = w_reg[nxt];
      if (t < 128) {
        sm->As[nxt][lcA+0][lrA] = an.x; sm->As[nxt][lcA+1][lrA] = an.y;
        sm->As[nxt][lcA+2][lrA] = an.z; sm->As[nxt][lcA+3][lrA] = an.w;
      }
      sm->Ws[nxt][lcA+0][lrA] = wn4.x; sm->Ws[nxt][lcA+1][lrA] = wn4.y;
      sm->Ws[nxt][lcA+2][lrA] = wn4.z; sm->Ws[nxt][lcA+3][lrA] = wn4.w;
    }
    __syncthreads();
  }
  int m = m0 + ty*2, n = n0 + tx*4;
  float r0[4], r1[4];
#pragma unroll
  for (int j = 0; j < 4; j++) {
    float lo, hi; unpack2(acc[j], lo, hi);
    float bv = bias ? bias[n+j] : 0.f;
    float v0 = lo*alpha + bv;
    float v1 = hi*alpha + bv;
    if (relu) { v0 = fmaxf(v0, 0.f); v1 = fmaxf(v1, 0.f); }
    if (res)  { v0 += res[(size_t)m*Ncols + n+j]; v1 += res[(size_t)(m+1)*Ncols + n+j]; }
    r0[j] = v0; r1[j] = v1;
  }
  *(float4*)(C + (size_t)m*ldc + n)     = make_float4(r0[0], r0[1], r0[2], r0[3]);
  *(float4*)(C + (size_t)(m+1)*ldc + n) = make_float4(r1[0], r1[1], r1[2], r1[3]);
  __syncthreads();
}

// ---------------- device fn: MHA unit (b, h, i0) ----------------
__device__ void dev_mha(char* smraw, const float* __restrict__ qkv, float* __restrict__ out,
                        int S, int Bb, int b, int h, int i0) {
  float* smbuf = (float*)smraw;
  float* qs = smbuf;
  float* ks = qs + 64*48;
  float* vs = ks + S*48;
  float* sc = vs + S*48;
  int t = threadIdx.x;
  for (int i = t; i < 64*48; i += 256) {
    int s = i / 48, e = i - s*48;
    qs[i] = qkv[((size_t)(i0+s)*Bb + b)*576 + h*48 + e];
  }
  for (int i = t; i < S*48; i += 256) {
    int s = i / 48, e = i - s*48;
    size_t ro = ((size_t)s*Bb + b)*576 + h*48 + e;
    ks[i] = qkv[ro + 192]; vs[i] = qkv[ro + 384];
  }
  __syncthreads();
  const float scale = 0.14433756729740643f;
  {
    int iq = t >> 2, s4 = t & 3;
    float4 qreg[12];
#pragma unroll
    for (int j = 0; j < 12; j++) qreg[j] = *(const float4*)(qs + iq*48 + j*4);
    for (int s = s4; s < S; s += 4) {
      const float4* kr = (const float4*)(ks + s*48);
      ull pp = 0;
#pragma unroll
      for (int j = 0; j < 12; j++) {
        float4 kx = kr[j];
        ffma2(pp, pack2(qreg[j].x, qreg[j].y), pack2(kx.x, kx.y));
        ffma2(pp, pack2(qreg[j].z, qreg[j].w), pack2(kx.z, kx.w));
      }
      float lo, hi; unpack2(pp, lo, hi);
      sc[iq*S + s] = (lo + hi) * scale;
    }
  }
  __syncthreads();
  int warp = t >> 5, lane = t & 31;
  for (int i = warp; i < 64; i += 8) {
    float mx = -1e30f;
    for (int s = lane; s < S; s += 32) mx = fmaxf(mx, sc[i*S+s]);
#pragma unroll
    for (int o = 16; o; o >>= 1) mx = fmaxf(mx, __shfl_xor_sync(0xffffffffu, mx, o));
    float sum = 0.f;
    for (int s = lane; s < S; s += 32) { float e = __expf(sc[i*S+s]-mx); sc[i*S+s]=e; sum += e; }
#pragma unroll
    for (int o = 16; o; o >>= 1) sum += __shfl_xor_sync(0xffffffffu, sum, o);
    float r = 1.f / sum;
    for (int s = lane; s < S; s += 32) sc[i*S+s] *= r;
  }
  __syncthreads();
  for (int idx = t; idx < 64*12; idx += 256) {
    int i = idx / 12, e4 = idx - i*12;
    ull a0 = 0, a1 = 0;
    const float* vcol = vs + e4*4;
#pragma unroll 4
    for (int s = 0; s < S; s++) {
      ull w2 = dup2(sc[i*S + s]);
      float4 vv = *(const float4*)(vcol + s*48);
      ffma2(a0, w2, pack2(vv.x, vv.y));
      ffma2(a1, w2, pack2(vv.z, vv.w));
    }
    float o0, o1, o2, o3;
    unpack2(a0, o0, o1); unpack2(a1, o2, o3);
    *(float4*)(out + ((size_t)(i0+i)*Bb + b)*192 + h*48 + e4*4) = make_float4(o0, o1, o2, o3);
  }
  __syncthreads();
}

// ---------------- mega_front: weight pre-products + qt ----------------
__global__ __launch_bounds__(256)
void mega_front(const float* __restrict__ wk, const float* __restrict__ wq,
                const float* __restrict__ wo, const float* __restrict__ wv,
                const float* __restrict__ prev_slots,
                const float* __restrict__ lnq_g, const float* __restrict__ lnq_b,
                float* __restrict__ wkq, float* __restrict__ wvo, float* __restrict__ qt) {
  extern __shared__ __align__(16) char smraw[];
  int cta = blockIdx.x;
  // stage A: 36 tiles (2 matmuls x 6x3)
  if (cta < 36) {
    int z = cta / 18, r = cta - z*18;
    dev_mm192(smraw, z ? wo : wk, z ? wv : wq, z ? wvo : wkq, z ? 0 : 1, r / 3, r % 3);
  }
  grid_sync(NB_FRONT);
  // stage B: qt = isq * LN(prev_slots) @ wkq^T, 96 tiles
  dev_gemm_ln(smraw, prev_slots, wkq, nullptr, lnq_g, lnq_b, qt, DD,
              0.07216878364870323f, 0, 0, cta / 3, cta % 3);
}

// ---------------- psb_stream (R12/R14-proven) ----------------
__global__ __launch_bounds__(512)
void psb_stream_kernel(const float* __restrict__ features, const float* __restrict__ qt,
                       const float* __restrict__ g, const float* __restrict__ b,
                       float* __restrict__ y, float* __restrict__ den) {
  __shared__ ull   qgp[4*DD];
  __shared__ float s1s[NS], bbs[NS];
  __shared__ float ysum[NS*DD];
  __shared__ float csum[NS], dsum[NS];
  int bt = blockIdx.x, q4 = blockIdx.y;
  int t = threadIdx.x, wid = t >> 5, lane = t & 31;
  const float* qtb = qt + (size_t)bt*NS*DD;
  for (int i = t; i < 4*DD; i += 512) {
    int m = i / DD, c = i - m*DD;
    float gc = g[c];
    qgp[m*DD + c] = pack2(gc*qtb[(2*m)*DD + c], gc*qtb[(2*m+1)*DD + c]);
  }
  if (wid < 8) {
    int n = wid;
    float s1 = 0.f, bbv = 0.f;
#pragma unroll
    for (int j = 0; j < 6; j++) {
      int c = j*32 + lane;
      float qv = qtb[n*DD + c];
      s1 += g[c]*qv; bbv += b[c]*qv;
    }
#pragma unroll
    for (int o = 16; o; o >>= 1) {
      s1  += __shfl_xor_sync(0xffffffffu, s1,  o);
      bbv += __shfl_xor_sync(0xffffffffu, bbv, o);
    }
    if (lane == 0) { s1s[n] = s1; bbs[n] = bbv; }
  }
  for (int i = t; i < NS*DD; i += 512) ysum[i] = 0.f;
  if (t < NS) { csum[t] = 0.f; dsum[t] = 0.f; }
  __syncthreads();

  ull s1p[4], bp[4];
#pragma unroll
  for (int m = 0; m < 4; m++) {
    s1p[m] = pack2(s1s[2*m], s1s[2*m+1]);
    bp[m]  = pack2(bbs[2*m], bbs[2*m+1]);
  }
  ull yacc[4][6] = {};
  ull dacc[4] = {};
  ull cacc[4] = {};
  const float* fb = features + (size_t)bt * LL * DD;
  int s_begin = q4*256 + wid;
  int s_end   = q4*256 + 256;
  float vn[6];
  {
    const float* xr = fb + (size_t)s_begin * DD;
#pragma unroll
    for (int j = 0; j < 6; j++) vn[j] = xr[j*32 + lane];
  }
  for (int s = s_begin; s < s_end; s += 16) {
    float v[6];
#pragma unroll
    for (int j = 0; j < 6; j++) v[j] = vn[j];
    int s2i = s + 16;
    if (s2i < s_end) {
      const float* xr = fb + (size_t)s2i * DD;
#pragma unroll
      for (int j = 0; j < 6; j++) vn[j] = xr[j*32 + lane];
    }
    float sm = 0.f, sq = 0.f;
#pragma unroll
    for (int j = 0; j < 6; j++) { sm += v[j]; sq += v[j]*v[j]; }
    ull msq = pack2(sm, sq);
    ull dd[4] = {};
#pragma unroll
    for (int mI = 0; mI < 4; mI++) {
#pragma unroll
      for (int j = 0; j < 6; j++)
        ffma2(dd[mI], dup2(v[j]), qgp[mI*DD + j*32 + lane]);
    }
#pragma unroll
    for (int o = 16; o; o >>= 1) {
      msq = add2(msq, __shfl_xor_sync(0xffffffffu, msq, o));
#pragma unroll
      for (int mI = 0; mI < 4; mI++)
        dd[mI] = add2(dd[mI], __shfl_xor_sync(0xffffffffu, dd[mI], o));
    }
    unpack2(msq, sm, sq);
    float mean = sm * (1.f/DD);
    float inv = rsqrtf(fmaxf(sq*(1.f/DD) - mean*mean, 0.f) + 1e-5f);
    float nim = -inv*mean;
    float p[NS];
#pragma unroll
    for (int mI = 0; mI < 4; mI++) {
      ull pp = bp[mI];
      ffma2(pp, dd[mI], dup2(inv));
      ffma2(pp, s1p[mI], dup2(nim));
      unpack2(pp, p[2*mI], p[2*mI+1]);
    }
    float mx = p[0];
#pragma unroll
    for (int n = 1; n < NS; n++) mx = fmaxf(mx, p[n]);
    float ssum = 0.f;
#pragma unroll
    for (int n = 0; n < NS; n++) { p[n] = __expf(p[n]-mx); ssum += p[n]; }
    float r = 1.f / ssum;
#pragma unroll
    for (int mI = 0; mI < 4; mI++) {
      ull w2 = pack2(p[2*mI]*r, p[2*mI+1]*r);
      dacc[mI] = add2(dacc[mI], w2);
      ull wiv = mul2(w2, dup2(inv));
      ffma2(cacc[mI], wiv, dup2(mean));
#pragma unroll
      for (int j = 0; j < 6; j++) ffma2(yacc[mI][j], dup2(v[j]), wiv);
    }
  }
#pragma unroll
  for (int mI = 0; mI < 4; mI++) {
#pragma unroll
    for (int j = 0; j < 6; j++) {
      float lo, hi; unpack2(yacc[mI][j], lo, hi);
      atomicAdd(&ysum[(2*mI)*DD + j*32 + lane], lo);
      atomicAdd(&ysum[(2*mI+1)*DD + j*32 + lane], hi);
    }
  }
  if (lane == 0) {
#pragma unroll
    for (int mI = 0; mI < 4; mI++) {
      float lo, hi;
      unpack2(dacc[mI], lo, hi);
      atomicAdd(&dsum[2*mI], lo); atomicAdd(&dsum[2*mI+1], hi);
      unpack2(cacc[mI], lo, hi);
      atomicAdd(&csum[2*mI], lo); atomicAdd(&csum[2*mI+1], hi);
    }
  }
  __syncthreads();
  float* yp = y + (size_t)q4 * ROWS_S * DD + (size_t)bt*NS*DD;
  for (int i = t; i < NS*DD; i += 512) {
    int n = i / DD, d = i - n*DD;
    yp[i] = g[d]*(ysum[i] - csum[n]) + b[d]*dsum[n];
  }
  if (t < NS) den[q4*ROWS_S + bt*NS + t] = dsum[t];
}

// ---------------- mega_tail: everything after psb_stream ----------------
__global__ __launch_bounds__(256)
void mega_tail(const float* __restrict__ y, const float* __restrict__ den,
               const float* __restrict__ wvo, const float* __restrict__ prev_slots,
               const float* __restrict__ lnt_g, const float* __restrict__ lnt_b,
               const float* __restrict__ t_in_w, const float* __restrict__ t_in_b,
               const float* __restrict__ t_out_w, const float* __restrict__ t_out_b,
               const float* __restrict__ lno_g, const float* __restrict__ lno_b,
               const float* __restrict__ o_in_w, const float* __restrict__ o_in_b,
               const float* __restrict__ o_out_w, const float* __restrict__ o_out_b,
               const float* __restrict__ lnp_g, const float* __restrict__ lnp_b,
               const float* __restrict__ w1, const float* __restrict__ b1,
               const float* __restrict__ w2, const float* __restrict__ b2,
               float* __restrict__ t1, float* __restrict__ t2,
               float* __restrict__ qkvb, float* __restrict__ hid,
               float* __restrict__ outp) {
  extern __shared__ __align__(16) char smraw[];
  int cta = blockIdx.x;

  // S1: t1 = (sum_p y_p / sum_p den_p) @ wvo^T  (96 tiles)
  if (cta < 96) dev_gemm_s(smraw, y, wvo, nullptr, nullptr, den, t1,
                           DD, DD, DD, 1.f, 0, NPART, cta / 3, cta % 3);
  grid_sync(NB_TAIL);
  // S2: qkvb = LN(t1;lnt) @ t_in_w^T + b  (288 tiles)
  for (int i = cta; i < 288; i += NB_TAIL)
    dev_gemm_ln(smraw, t1, t_in_w, t_in_b, lnt_g, lnt_b, qkvb, 576, 1.f, 0, 0, i / 9, i % 9);
  grid_sync(NB_TAIL);
  // S3: time MHA (S=128, Bb=8): 64 units -> t1
  if (cta < 64) {
    int bh = cta & 31, chunk = cta >> 5;
    dev_mha(smraw, qkvb, t1, 128, 8, bh >> 2, bh & 3, chunk * 64);
  }
  grid_sync(NB_TAIL);
  // S4: t2 = t1 @ t_out_w^T + b  (96 tiles)
  if (cta < 96) dev_gemm_s(smraw, t1, t_out_w, t_out_b, nullptr, nullptr, t2,
                           DD, DD, DD, 1.f, 0, 1, cta / 3, cta % 3);
  grid_sync(NB_TAIL);
  // S5: qkvb = LN(perm(t2);lno) @ o_in_w^T + b  (288 tiles)
  for (int i = cta; i < 288; i += NB_TAIL)
    dev_gemm_ln(smraw, t2, o_in_w, o_in_b, lno_g, lno_b, qkvb, 576, 1.f, 0, 1, i / 9, i % 9);
  grid_sync(NB_TAIL);
  // S6: object MHA (S=64, Bb=16): 64 units -> t1
  if (cta < 64) dev_mha(smraw, qkvb, t1, 64, 16, cta >> 2, cta & 3, 0);
  grid_sync(NB_TAIL);
  // S7: t2 = t1 @ o_out_w^T + b  (96 tiles)
  if (cta < 96) dev_gemm_s(smraw, t1, o_out_w, o_out_b, nullptr, nullptr, t2,
                           DD, DD, DD, 1.f, 0, 1, cta / 3, cta % 3);
  grid_sync(NB_TAIL);
  // S8: hid = relu(LN(t2;lnp) @ w1^T + b1)  (256 tiles, N=512)
  for (int i = cta; i < 256; i += NB_TAIL)
    dev_gemm_ln(smraw, t2, w1, b1, lnp_g, lnp_b, hid, 512, 1.f, 1, 0, i / 8, i % 8);
  grid_sync(NB_TAIL);
  // S9: out = hid @ w2^T + b2 + prev_slots  (96 tiles, K=512)
  if (cta < 96) dev_gemm_s(smraw, hid, w2, b2, prev_slots, nullptr, outp,
                           DD, 512, DD, 1.f, 0, 1, cta / 3, cta % 3);
}

// ---------------- launcher ----------------
extern "C" void kernel_launch(void* const* d_in, const int* in_sizes, int n_in,
                              void* d_out, int out_size) {
  const float* features   = (const float*)d_in[0];
  const float* prev_slots = (const float*)d_in[1];
  const float* lnq_g  = (const float*)d_in[2],  *lnq_b  = (const float*)d_in[3];
  const float* lnkv_g = (const float*)d_in[4],  *lnkv_b = (const float*)d_in[5];
  const float* wq = (const float*)d_in[6],  *wk = (const float*)d_in[7];
  const float* wvw= (const float*)d_in[8],  *wo = (const float*)d_in[9];
  const float* lnt_g  = (const float*)d_in[10], *lnt_b  = (const float*)d_in[11];
  const float* t_in_w = (const float*)d_in[12], *t_in_b = (const float*)d_in[13];
  const float* t_out_w= (const float*)d_in[14], *t_out_b= (const float*)d_in[15];
  const float* lno_g  = (const float*)d_in[16], *lno_b  = (const float*)d_in[17];
  const float* o_in_w = (const float*)d_in[18], *o_in_b = (const float*)d_in[19];
  const float* o_out_w= (const float*)d_in[20], *o_out_b= (const float*)d_in[21];
  const float* lnp_g  = (const float*)d_in[22], *lnp_b  = (const float*)d_in[23];
  const float* w1 = (const float*)d_in[24], *b1 = (const float*)d_in[25];
  const float* w2 = (const float*)d_in[26], *b2 = (const float*)d_in[27];
  float* outp = (float*)d_out;

  float *qt, *wkq, *wvo, *y, *den, *t1, *t2, *qkvb, *hid;
  cudaGetSymbolAddress((void**)&qt,   g_qt);
  cudaGetSymbolAddress((void**)&wkq,  g_wkq);
  cudaGetSymbolAddress((void**)&wvo,  g_wvo);
  cudaGetSymbolAddress((void**)&y,    g_y);
  cudaGetSymbolAddress((void**)&den,  g_den);
  cudaGetSymbolAddress((void**)&t1,   g_t1);
  cudaGetSymbolAddress((void**)&t2,   g_t2);
  cudaGetSymbolAddress((void**)&qkvb, g_qkvb);
  cudaGetSymbolAddress((void**)&hid,  g_hid);

  cudaFuncSetAttribute(mega_front, cudaFuncAttributeMaxDynamicSharedMemorySize, (int)SM_FRONT_BYTES);
  cudaFuncSetAttribute(mega_tail,  cudaFuncAttributeMaxDynamicSharedMemorySize, SM_MHA_BYTES);

  // (1) weight pre-products + qt  [1 launch, internal barrier]
  mega_front<<<NB_FRONT, 256, SM_FRONT_BYTES>>>(wk, wq, wo, wvw, prev_slots,
                                                lnq_g, lnq_b, wkq, wvo, qt);
  // (2) fused LN + inverse cross-attention stream (reads features once)
  psb_stream_kernel<<<dim3(BT, NPART), 512>>>(features, qt, lnkv_g, lnkv_b, y, den);
  // (3) everything else  [1 persistent launch, 8 internal barriers]
  mega_tail<<<NB_TAIL, 256, SM_MHA_BYTES>>>(y, den, wvo, prev_slots,
                                            lnt_g, lnt_b, t_in_w, t_in_b, t_out_w, t_out_b,
                                            lno_g, lno_b, o_in_w, o_in_b, o_out_w, o_out_b,
                                            lnp_g, lnp_b, w1, b1, w2, b2,
                                            t1, t2, qkvb, hid, outp);
}

// round 16
// speedup vs baseline: 1.1209x; 1.1209x over previous
#include <cuda_runtime.h>
#include <cstdint>

#define DD 192
#define LL 1024
#define BT 128
#define NS 8
#define ROWS_S   (BT*NS)   /* 1024 */
#define NPART 4

typedef unsigned long long ull;

// ---------------- scratch (device globals; no allocs allowed) ----------------
__device__ float g_qt  [ROWS_S * DD];
__device__ float g_wkq [DD * DD];
__device__ float g_wvo [DD * DD];
__device__ float g_y   [NPART * ROWS_S * DD];
__device__ float g_den [NPART * ROWS_S];
__device__ float g_t1  [ROWS_S * DD];
__device__ float g_t2  [ROWS_S * DD];
__device__ float g_qkvb[ROWS_S * 576];
__device__ float g_hid [ROWS_S * 512];
__device__ int   g_bar = 0;
__device__ int   g_gen = 0;

// ---------------- packed f32x2 helpers ----------------
__device__ __forceinline__ ull dup2(float x) {
  ull r; asm("mov.b64 %0, {%1, %1};" : "=l"(r) : "f"(x)); return r;
}
__device__ __forceinline__ ull pack2(float lo, float hi) {
  ull r; asm("mov.b64 %0, {%1, %2};" : "=l"(r) : "f"(lo), "f"(hi)); return r;
}
__device__ __forceinline__ void unpack2(ull v, float& lo, float& hi) {
  asm("mov.b64 {%0, %1}, %2;" : "=f"(lo), "=f"(hi) : "l"(v));
}
__device__ __forceinline__ void ffma2(ull& d, ull a, ull b) {
  asm("fma.rn.f32x2 %0, %1, %2, %0;" : "+l"(d) : "l"(a), "l"(b));
}
__device__ __forceinline__ ull add2(ull a, ull b) {
  ull r; asm("add.rn.f32x2 %0, %1, %2;" : "=l"(r) : "l"(a), "l"(b)); return r;
}
__device__ __forceinline__ ull mul2(ull a, ull b) {
  ull r; asm("mul.rn.f32x2 %0, %1, %2;" : "=l"(r) : "l"(a), "l"(b)); return r;
}

// ---------------- grid-wide barrier (all CTAs resident: grid sized by occupancy) ----------------
__device__ __forceinline__ void grid_sync() {
  __syncthreads();
  if (threadIdx.x == 0) {
    volatile int* genp = &g_gen;
    int gen = *genp;
    __threadfence();
    if (atomicAdd(&g_bar, 1) == (int)gridDim.x - 1) {
      g_bar = 0;
      __threadfence();
      *genp = gen + 1;
    } else {
      while (*genp == gen) { }
    }
  }
  __syncthreads();
}

// ---------------- smem layouts ----------------
struct SmLn { float Af[32][193]; __align__(16) float Ws[2][16][68]; float gs[DD], bs[DD]; };
struct SmGs { __align__(16) float As[2][16][36]; __align__(16) float Ws[2][16][68]; };
#define SM_MHA_BYTES ((64*48 + 2*128*48 + 64*128)*4)

// ---------------- device fn: fused LN + GEMM tile (K=192) ----------------
__device__ void dev_gemm_ln(char* smraw,
                            const float* __restrict__ A, const float* __restrict__ W,
                            const float* __restrict__ bias,
                            const float* __restrict__ gamma, const float* __restrict__ beta,
                            float* __restrict__ C, int ldc, float alpha, int relu, int perm,
                            int tm, int tn) {
  SmLn* sm = (SmLn*)smraw;
  int t = threadIdx.x;
  int m0 = tm * 32, n0 = tn * 64;
  int lw = t >> 2, lk = (t & 3) << 2;
  const float* Wp = W + (size_t)(n0 + lw)*DD + lk;
  float4 w_reg[2];
  w_reg[0] = *(const float4*)(Wp + 0);
  w_reg[1] = *(const float4*)(Wp + 16);
  for (int i = t; i < DD; i += 256) { sm->gs[i] = gamma[i]; sm->bs[i] = beta[i]; }
  for (int i = t; i < 32*DD; i += 256) {
    int r = i / DD, c = i - r*DD;
    int sr = m0 + r;
    if (perm) { int w = sr; int bb = w >> 7, n = (w >> 4) & 7, tt = w & 15; sr = (bb*16 + tt)*8 + n; }
    sm->Af[r][c] = A[(size_t)sr*DD + c];
  }
  __syncthreads();
  int wid = t >> 5, lane = t & 31;
#pragma unroll
  for (int i = 0; i < 4; i++) {
    int r = wid*4 + i;
    float s = 0.f, s2 = 0.f;
#pragma unroll
    for (int c0 = 0; c0 < 6; c0++) { float v = sm->Af[r][c0*32 + lane]; s += v; s2 += v*v; }
#pragma unroll
    for (int o = 16; o; o >>= 1) {
      s  += __shfl_xor_sync(0xffffffffu, s,  o);
      s2 += __shfl_xor_sync(0xffffffffu, s2, o);
    }
    float m = s * (1.f/DD);
    float inv = rsqrtf(fmaxf(s2*(1.f/DD) - m*m, 0.f) + 1e-5f);
#pragma unroll
    for (int c0 = 0; c0 < 6; c0++) {
      int c = c0*32 + lane;
      sm->Af[r][c] = (sm->Af[r][c] - m)*inv*sm->gs[c] + sm->bs[c];
    }
  }
  sm->Ws[0][lk+0][lw] = w_reg[0].x; sm->Ws[0][lk+1][lw] = w_reg[0].y;
  sm->Ws[0][lk+2][lw] = w_reg[0].z; sm->Ws[0][lk+3][lw] = w_reg[0].w;
  __syncthreads();

  int ty = t >> 4, tx = t & 15;
  ull acc[4] = {};
  const int NK = 12;
  for (int i = 0; i < NK; i++) {
    int cur = i & 1;
    if (i + 2 < NK) w_reg[cur] = *(const float4*)(Wp + (i+2)*16);
#pragma unroll
    for (int k = 0; k < 16; k++) {
      ull ap = pack2(sm->Af[ty*2][i*16+k], sm->Af[ty*2+1][i*16+k]);
      float4 w4 = *(const float4*)&sm->Ws[cur][k][tx*4];
      ffma2(acc[0], ap, dup2(w4.x));
      ffma2(acc[1], ap, dup2(w4.y));
      ffma2(acc[2], ap, dup2(w4.z));
      ffma2(acc[3], ap, dup2(w4.w));
    }
    if (i + 1 < NK) {
      int nxt = (i+1) & 1;
      float4 wn4 = w_reg[nxt];
      sm->Ws[nxt][lk+0][lw] = wn4.x; sm->Ws[nxt][lk+1][lw] = wn4.y;
      sm->Ws[nxt][lk+2][lw] = wn4.z; sm->Ws[nxt][lk+3][lw] = wn4.w;
    }
    __syncthreads();
  }
  int m = m0 + ty*2, n = n0 + tx*4;
  float r0[4], r1[4];
#pragma unroll
  for (int j = 0; j < 4; j++) {
    float lo, hi; unpack2(acc[j], lo, hi);
    float bv = bias ? bias[n+j] : 0.f;
    float v0 = lo*alpha + bv;
    float v1 = hi*alpha + bv;
    if (relu) { v0 = fmaxf(v0, 0.f); v1 = fmaxf(v1, 0.f); }
    r0[j] = v0; r1[j] = v1;
  }
  *(float4*)(C + (size_t)m*ldc + n)     = make_float4(r0[0], r0[1], r0[2], r0[3]);
  *(float4*)(C + (size_t)(m+1)*ldc + n) = make_float4(r1[0], r1[1], r1[2], r1[3]);
  __syncthreads();
}

// ---------------- device fn: small-tile GEMM (double-buffered) ----------------
__device__ void dev_gemm_s(char* smraw,
                           const float* __restrict__ A, const float* __restrict__ W,
                           const float* __restrict__ bias, const float* __restrict__ res,
                           const float* __restrict__ rowdiv,
                           float* __restrict__ C, int Ncols, int K, int ldc,
                           float alpha, int relu, int nacc, int tm, int tn) {
  SmGs* sm = (SmGs*)smraw;
  int t = threadIdx.x;
  int m0 = tm * 32, n0 = tn * 64;
  int lrA = t >> 2, lcA = (t & 3) << 2;
  const float* Ap = A + (size_t)(m0 + (lrA & 31)) * K + lcA;
  const float* Wp = W + (size_t)(n0 + lrA) * K + lcA;
  float rsA = 1.f;
  if (rowdiv && t < 128) {
    float d = 0.f;
    for (int p = 0; p < nacc; p++) d += rowdiv[p*ROWS_S + m0 + lrA];
    rsA = 1.f / d;
  }
  int ty = t >> 4, tx = t & 15;
  int NK = K >> 4;
  ull acc[4] = {};
  float4 a_reg[2], w_reg[2];
  auto loadT = [&](int i, float4& a0, float4& w0) {
    a0 = make_float4(0.f,0.f,0.f,0.f);
    if (t < 128) {
      a0 = *(const float4*)(Ap + i*16);
      for (int p = 1; p < nacc; p++) {
        float4 a2 = *(const float4*)(Ap + (size_t)p*ROWS_S*DD + i*16);
        a0.x += a2.x; a0.y += a2.y; a0.z += a2.z; a0.w += a2.w;
      }
      a0.x *= rsA; a0.y *= rsA; a0.z *= rsA; a0.w *= rsA;
    }
    w0 = *(const float4*)(Wp + i*16);
  };
  loadT(0, a_reg[0], w_reg[0]);
  if (NK > 1) loadT(1, a_reg[1], w_reg[1]);
  if (t < 128) {
    sm->As[0][lcA+0][lrA] = a_reg[0].x; sm->As[0][lcA+1][lrA] = a_reg[0].y;
    sm->As[0][lcA+2][lrA] = a_reg[0].z; sm->As[0][lcA+3][lrA] = a_reg[0].w;
  }
  sm->Ws[0][lcA+0][lrA] = w_reg[0].x; sm->Ws[0][lcA+1][lrA] = w_reg[0].y;
  sm->Ws[0][lcA+2][lrA] = w_reg[0].z; sm->Ws[0][lcA+3][lrA] = w_reg[0].w;
  __syncthreads();
  for (int i = 0; i < NK; i++) {
    int cur = i & 1;
    if (i + 2 < NK) loadT(i+2, a_reg[cur], w_reg[cur]);
#pragma unroll
    for (int k = 0; k < 16; k++) {
      ull ap = *(const ull*)&sm->As[cur][k][ty*2];
      float4 wv = *(const float4*)&sm->Ws[cur][k][tx*4];
      ffma2(acc[0], ap, dup2(wv.x));
      ffma2(acc[1], ap, dup2(wv.y));
      ffma2(acc[2], ap, dup2(wv.z));
      ffma2(acc[3], ap, dup2(wv.w));
    }
    if (i + 1 < NK) {
      int nxt = (i+1) & 1;
      float4 an = a_reg[nxt], wn4 = w_reg[nxt];
      if (t < 128) {
        sm->As[nxt][lcA+0][lrA] = an.x; sm->As[nxt][lcA+1][lrA] = an.y;
        sm->As[nxt][lcA+2][lrA] = an.z; sm->As[nxt][lcA+3][lrA] = an.w;
      }
      sm->Ws[nxt][lcA+0][lrA] = wn4.x; sm->Ws[nxt][lcA+1][lrA] = wn4.y;
      sm->Ws[nxt][lcA+2][lrA] = wn4.z; sm->Ws[nxt][lcA+3][lrA] = wn4.w;
    }
    __syncthreads();
  }
  int m = m0 + ty*2, n = n0 + tx*4;
  float r0[4], r1[4];
#pragma unroll
  for (int j = 0; j < 4; j++) {
    float lo, hi; unpack2(acc[j], lo, hi);
    float bv = bias ? bias[n+j] : 0.f;
    float v0 = lo*alpha + bv;
    float v1 = hi*alpha + bv;
    if (relu) { v0 = fmaxf(v0, 0.f); v1 = fmaxf(v1, 0.f); }
    if (res)  { v0 += res[(size_t)m*Ncols + n+j]; v1 += res[(size_t)(m+1)*Ncols + n+j]; }
    r0[j] = v0; r1[j] = v1;
  }
  *(float4*)(C + (size_t)m*ldc + n)     = make_float4(r0[0], r0[1], r0[2], r0[3]);
  *(float4*)(C + (size_t)(m+1)*ldc + n) = make_float4(r1[0], r1[1], r1[2], r1[3]);
  __syncthreads();
}

// ---------------- device fn: MHA unit (b, h, i0) ----------------
__device__ void dev_mha(char* smraw, const float* __restrict__ qkv, float* __restrict__ out,
                        int S, int Bb, int b, int h, int i0) {
  float* smbuf = (float*)smraw;
  float* qs = smbuf;
  float* ks = qs + 64*48;
  float* vs = ks + S*48;
  float* sc = vs + S*48;
  int t = threadIdx.x;
  for (int i = t; i < 64*48; i += 256) {
    int s = i / 48, e = i - s*48;
    qs[i] = qkv[((size_t)(i0+s)*Bb + b)*576 + h*48 + e];
  }
  for (int i = t; i < S*48; i += 256) {
    int s = i / 48, e = i - s*48;
    size_t ro = ((size_t)s*Bb + b)*576 + h*48 + e;
    ks[i] = qkv[ro + 192]; vs[i] = qkv[ro + 384];
  }
  __syncthreads();
  const float scale = 0.14433756729740643f;
  {
    int iq = t >> 2, s4 = t & 3;
    float4 qreg[12];
#pragma unroll
    for (int j = 0; j < 12; j++) qreg[j] = *(const float4*)(qs + iq*48 + j*4);
    for (int s = s4; s < S; s += 4) {
      const float4* kr = (const float4*)(ks + s*48);
      ull pp = 0;
#pragma unroll
      for (int j = 0; j < 12; j++) {
        float4 kx = kr[j];
        ffma2(pp, pack2(qreg[j].x, qreg[j].y), pack2(kx.x, kx.y));
        ffma2(pp, pack2(qreg[j].z, qreg[j].w), pack2(kx.z, kx.w));
      }
      float lo, hi; unpack2(pp, lo, hi);
      sc[iq*S + s] = (lo + hi) * scale;
    }
  }
  __syncthreads();
  int warp = t >> 5, lane = t & 31;
  for (int i = warp; i < 64; i += 8) {
    float mx = -1e30f;
    for (int s = lane; s < S; s += 32) mx = fmaxf(mx, sc[i*S+s]);
#pragma unroll
    for (int o = 16; o; o >>= 1) mx = fmaxf(mx, __shfl_xor_sync(0xffffffffu, mx, o));
    float sum = 0.f;
    for (int s = lane; s < S; s += 32) { float e = __expf(sc[i*S+s]-mx); sc[i*S+s]=e; sum += e; }
#pragma unroll
    for (int o = 16; o; o >>= 1) sum += __shfl_xor_sync(0xffffffffu, sum, o);
    float r = 1.f / sum;
    for (int s = lane; s < S; s += 32) sc[i*S+s] *= r;
  }
  __syncthreads();
  for (int idx = t; idx < 64*12; idx += 256) {
    int i = idx / 12, e4 = idx - i*12;
    ull a0 = 0, a1 = 0;
    const float* vcol = vs + e4*4;
#pragma unroll 4
    for (int s = 0; s < S; s++) {
      ull w2 = dup2(sc[i*S + s]);
      float4 vv = *(const float4*)(vcol + s*48);
      ffma2(a0, w2, pack2(vv.x, vv.y));
      ffma2(a1, w2, pack2(vv.z, vv.w));
    }
    float o0, o1, o2, o3;
    unpack2(a0, o0, o1); unpack2(a1, o2, o3);
    *(float4*)(out + ((size_t)(i0+i)*Bb + b)*192 + h*48 + e4*4) = make_float4(o0, o1, o2, o3);
  }
  __syncthreads();
}

// ---------------- standalone front kernels (R14-proven) ----------------
__global__ __launch_bounds__(256)
void mm192_dual_kernel(const float* __restrict__ wk, const float* __restrict__ wq,
                       const float* __restrict__ wo, const float* __restrict__ wv,
                       float* __restrict__ wkq, float* __restrict__ wvo) {
  int z = blockIdx.z;
  const float* A = z ? wo : wk;
  const float* B = z ? wv : wq;
  float* C = z ? wvo : wkq;
  int transA = z ? 0 : 1;
  __shared__ __align__(16) float As[16][34];
  __shared__ __align__(16) float Ws[16][68];
  int t = threadIdx.x;
  int m0 = blockIdx.x * 32, n0 = blockIdx.y * 64;
  int ty = t >> 4, tx = t & 15;
  ull acc[4] = {};
  int wn = t >> 2, wk2 = (t & 3) << 2;
  for (int k0 = 0; k0 < DD; k0 += 16) {
    float av[2]; int ak[2], am[2];
#pragma unroll
    for (int h = 0; h < 2; h++) {
      int i = t + h*256;
      ak[h] = i >> 5; am[h] = i & 31;
      av[h] = transA ? A[(size_t)(k0 + ak[h])*DD + m0 + am[h]]
                     : A[(size_t)(m0 + am[h])*DD + k0 + ak[h]];
    }
    float wv4[4];
#pragma unroll
    for (int j = 0; j < 4; j++) wv4[j] = B[(size_t)(k0 + wk2 + j)*DD + n0 + wn];
    __syncthreads();
#pragma unroll
    for (int h = 0; h < 2; h++) As[ak[h]][am[h]] = av[h];
#pragma unroll
    for (int j = 0; j < 4; j++) Ws[wk2 + j][wn] = wv4[j];
    __syncthreads();
#pragma unroll
    for (int k = 0; k < 16; k++) {
      ull ap = *(const ull*)&As[k][ty*2];
      float4 w4 = *(const float4*)&Ws[k][tx*4];
      ffma2(acc[0], ap, dup2(w4.x));
      ffma2(acc[1], ap, dup2(w4.y));
      ffma2(acc[2], ap, dup2(w4.z));
      ffma2(acc[3], ap, dup2(w4.w));
    }
  }
  int m = m0 + ty*2, n = n0 + tx*4;
  float r0[4], r1[4];
#pragma unroll
  for (int j = 0; j < 4; j++) unpack2(acc[j], r0[j], r1[j]);
  *(float4*)(C + (size_t)m*DD + n)     = make_float4(r0[0], r0[1], r0[2], r0[3]);
  *(float4*)(C + (size_t)(m+1)*DD + n) = make_float4(r1[0], r1[1], r1[2], r1[3]);
}

__global__ __launch_bounds__(256)
void gemm_ln_kernel(const float* __restrict__ A, const float* __restrict__ W,
                    const float* __restrict__ bias,
                    const float* __restrict__ gamma, const float* __restrict__ beta,
                    float* __restrict__ C, int ldc, float alpha, int relu, int perm) {
  __shared__ __align__(16) char smraw[sizeof(SmLn)];
  dev_gemm_ln(smraw, A, W, bias, gamma, beta, C, ldc, alpha, relu, perm,
              blockIdx.x, blockIdx.y);
}

// ---------------- psb_stream (R12/R14-proven) ----------------
__global__ __launch_bounds__(512)
void psb_stream_kernel(const float* __restrict__ features, const float* __restrict__ qt,
                       const float* __restrict__ g, const float* __restrict__ b,
                       float* __restrict__ y, float* __restrict__ den) {
  __shared__ ull   qgp[4*DD];
  __shared__ float s1s[NS], bbs[NS];
  __shared__ float ysum[NS*DD];
  __shared__ float csum[NS], dsum[NS];
  int bt = blockIdx.x, q4 = blockIdx.y;
  int t = threadIdx.x, wid = t >> 5, lane = t & 31;
  const float* qtb = qt + (size_t)bt*NS*DD;
  for (int i = t; i < 4*DD; i += 512) {
    int m = i / DD, c = i - m*DD;
    float gc = g[c];
    qgp[m*DD + c] = pack2(gc*qtb[(2*m)*DD + c], gc*qtb[(2*m+1)*DD + c]);
  }
  if (wid < 8) {
    int n = wid;
    float s1 = 0.f, bbv = 0.f;
#pragma unroll
    for (int j = 0; j < 6; j++) {
      int c = j*32 + lane;
      float qv = qtb[n*DD + c];
      s1 += g[c]*qv; bbv += b[c]*qv;
    }
#pragma unroll
    for (int o = 16; o; o >>= 1) {
      s1  += __shfl_xor_sync(0xffffffffu, s1,  o);
      bbv += __shfl_xor_sync(0xffffffffu, bbv, o);
    }
    if (lane == 0) { s1s[n] = s1; bbs[n] = bbv; }
  }
  for (int i = t; i < NS*DD; i += 512) ysum[i] = 0.f;
  if (t < NS) { csum[t] = 0.f; dsum[t] = 0.f; }
  __syncthreads();

  ull s1p[4], bp[4];
#pragma unroll
  for (int m = 0; m < 4; m++) {
    s1p[m] = pack2(s1s[2*m], s1s[2*m+1]);
    bp[m]  = pack2(bbs[2*m], bbs[2*m+1]);
  }
  ull yacc[4][6] = {};
  ull dacc[4] = {};
  ull cacc[4] = {};
  const float* fb = features + (size_t)bt * LL * DD;
  int s_begin = q4*256 + wid;
  int s_end   = q4*256 + 256;
  float vn[6];
  {
    const float* xr = fb + (size_t)s_begin * DD;
#pragma unroll
    for (int j = 0; j < 6; j++) vn[j] = xr[j*32 + lane];
  }
  for (int s = s_begin; s < s_end; s += 16) {
    float v[6];
#pragma unroll
    for (int j = 0; j < 6; j++) v[j] = vn[j];
    int s2i = s + 16;
    if (s2i < s_end) {
      const float* xr = fb + (size_t)s2i * DD;
#pragma unroll
      for (int j = 0; j < 6; j++) vn[j] = xr[j*32 + lane];
    }
    float sm = 0.f, sq = 0.f;
#pragma unroll
    for (int j = 0; j < 6; j++) { sm += v[j]; sq += v[j]*v[j]; }
    ull msq = pack2(sm, sq);
    ull dd[4] = {};
#pragma unroll
    for (int mI = 0; mI < 4; mI++) {
#pragma unroll
      for (int j = 0; j < 6; j++)
        ffma2(dd[mI], dup2(v[j]), qgp[mI*DD + j*32 + lane]);
    }
#pragma unroll
    for (int o = 16; o; o >>= 1) {
      msq = add2(msq, __shfl_xor_sync(0xffffffffu, msq, o));
#pragma unroll
      for (int mI = 0; mI < 4; mI++)
        dd[mI] = add2(dd[mI], __shfl_xor_sync(0xffffffffu, dd[mI], o));
    }
    unpack2(msq, sm, sq);
    float mean = sm * (1.f/DD);
    float inv = rsqrtf(fmaxf(sq*(1.f/DD) - mean*mean, 0.f) + 1e-5f);
    float nim = -inv*mean;
    float p[NS];
#pragma unroll
    for (int mI = 0; mI < 4; mI++) {
      ull pp = bp[mI];
      ffma2(pp, dd[mI], dup2(inv));
      ffma2(pp, s1p[mI], dup2(nim));
      unpack2(pp, p[2*mI], p[2*mI+1]);
    }
    float mx = p[0];
#pragma unroll
    for (int n = 1; n < NS; n++) mx = fmaxf(mx, p[n]);
    float ssum = 0.f;
#pragma unroll
    for (int n = 0; n < NS; n++) { p[n] = __expf(p[n]-mx); ssum += p[n]; }
    float r = 1.f / ssum;
#pragma unroll
    for (int mI = 0; mI < 4; mI++) {
      ull w2 = pack2(p[2*mI]*r, p[2*mI+1]*r);
      dacc[mI] = add2(dacc[mI], w2);
      ull wiv = mul2(w2, dup2(inv));
      ffma2(cacc[mI], wiv, dup2(mean));
#pragma unroll
      for (int j = 0; j < 6; j++) ffma2(yacc[mI][j], dup2(v[j]), wiv);
    }
  }
#pragma unroll
  for (int mI = 0; mI < 4; mI++) {
#pragma unroll
    for (int j = 0; j < 6; j++) {
      float lo, hi; unpack2(yacc[mI][j], lo, hi);
      atomicAdd(&ysum[(2*mI)*DD + j*32 + lane], lo);
      atomicAdd(&ysum[(2*mI+1)*DD + j*32 + lane], hi);
    }
  }
  if (lane == 0) {
#pragma unroll
    for (int mI = 0; mI < 4; mI++) {
      float lo, hi;
      unpack2(dacc[mI], lo, hi);
      atomicAdd(&dsum[2*mI], lo); atomicAdd(&dsum[2*mI+1], hi);
      unpack2(cacc[mI], lo, hi);
      atomicAdd(&csum[2*mI], lo); atomicAdd(&csum[2*mI+1], hi);
    }
  }
  __syncthreads();
  float* yp = y + (size_t)q4 * ROWS_S * DD + (size_t)bt*NS*DD;
  for (int i = t; i < NS*DD; i += 512) {
    int n = i / DD, d = i - n*DD;
    yp[i] = g[d]*(ysum[i] - csum[n]) + b[d]*dsum[n];
  }
  if (t < NS) den[q4*ROWS_S + bt*NS + t] = dsum[t];
}

// ---------------- mega_tail: everything after psb_stream (grid-strided stages) ----------------
__global__ __launch_bounds__(256)
void mega_tail(const float* __restrict__ y, const float* __restrict__ den,
               const float* __restrict__ wvo, const float* __restrict__ prev_slots,
               const float* __restrict__ lnt_g, const float* __restrict__ lnt_b,
               const float* __restrict__ t_in_w, const float* __restrict__ t_in_b,
               const float* __restrict__ t_out_w, const float* __restrict__ t_out_b,
               const float* __restrict__ lno_g, const float* __restrict__ lno_b,
               const float* __restrict__ o_in_w, const float* __restrict__ o_in_b,
               const float* __restrict__ o_out_w, const float* __restrict__ o_out_b,
               const float* __restrict__ lnp_g, const float* __restrict__ lnp_b,
               const float* __restrict__ w1, const float* __restrict__ b1,
               const float* __restrict__ w2, const float* __restrict__ b2,
               float* __restrict__ t1, float* __restrict__ t2,
               float* __restrict__ qkvb, float* __restrict__ hid,
               float* __restrict__ outp) {
  extern __shared__ __align__(16) char smraw[];
  int cta = blockIdx.x, gd = gridDim.x;

  // S1: t1 = (sum_p y_p / sum_p den_p) @ wvo^T  (96 tiles)
  for (int i = cta; i < 96; i += gd)
    dev_gemm_s(smraw, y, wvo, nullptr, nullptr, den, t1, DD, DD, DD, 1.f, 0, NPART, i / 3, i % 3);
  grid_sync();
  // S2: qkvb = LN(t1;lnt) @ t_in_w^T + b  (288 tiles)
  for (int i = cta; i < 288; i += gd)
    dev_gemm_ln(smraw, t1, t_in_w, t_in_b, lnt_g, lnt_b, qkvb, 576, 1.f, 0, 0, i / 9, i % 9);
  grid_sync();
  // S3: time MHA (S=128, Bb=8): 64 units -> t1
  for (int u = cta; u < 64; u += gd) {
    int bh = u & 31, chunk = u >> 5;
    dev_mha(smraw, qkvb, t1, 128, 8, bh >> 2, bh & 3, chunk * 64);
  }
  grid_sync();
  // S4: t2 = t1 @ t_out_w^T + b  (96 tiles)
  for (int i = cta; i < 96; i += gd)
    dev_gemm_s(smraw, t1, t_out_w, t_out_b, nullptr, nullptr, t2, DD, DD, DD, 1.f, 0, 1, i / 3, i % 3);
  grid_sync();
  // S5: qkvb = LN(perm(t2);lno) @ o_in_w^T + b  (288 tiles)
  for (int i = cta; i < 288; i += gd)
    dev_gemm_ln(smraw, t2, o_in_w, o_in_b, lno_g, lno_b, qkvb, 576, 1.f, 0, 1, i / 9, i % 9);
  grid_sync();
  // S6: object MHA (S=64, Bb=16): 64 units -> t1
  for (int u = cta; u < 64; u += gd)
    dev_mha(smraw, qkvb, t1, 64, 16, u >> 2, u & 3, 0);
  grid_sync();
  // S7: t2 = t1 @ o_out_w^T + b  (96 tiles)
  for (int i = cta; i < 96; i += gd)
    dev_gemm_s(smraw, t1, o_out_w, o_out_b, nullptr, nullptr, t2, DD, DD, DD, 1.f, 0, 1, i / 3, i % 3);
  grid_sync();
  // S8: hid = relu(LN(t2;lnp) @ w1^T + b1)  (256 tiles, N=512)
  for (int i = cta; i < 256; i += gd)
    dev_gemm_ln(smraw, t2, w1, b1, lnp_g, lnp_b, hid, 512, 1.f, 1, 0, i / 8, i % 8);
  grid_sync();
  // S9: out = hid @ w2^T + b2 + prev_slots  (96 tiles, K=512)
  for (int i = cta; i < 96; i += gd)
    dev_gemm_s(smraw, hid, w2, b2, prev_slots, nullptr, outp, DD, 512, DD, 1.f, 0, 1, i / 3, i % 3);
}

// ---------------- launcher ----------------
extern "C" void kernel_launch(void* const* d_in, const int* in_sizes, int n_in,
                              void* d_out, int out_size) {
  const float* features   = (const float*)d_in[0];
  const float* prev_slots = (const float*)d_in[1];
  const float* lnq_g  = (const float*)d_in[2],  *lnq_b  = (const float*)d_in[3];
  const float* lnkv_g = (const float*)d_in[4],  *lnkv_b = (const float*)d_in[5];
  const float* wq = (const float*)d_in[6],  *wk = (const float*)d_in[7];
  const float* wvw= (const float*)d_in[8],  *wo = (const float*)d_in[9];
  const float* lnt_g  = (const float*)d_in[10], *lnt_b  = (const float*)d_in[11];
  const float* t_in_w = (const float*)d_in[12], *t_in_b = (const float*)d_in[13];
  const float* t_out_w= (const float*)d_in[14], *t_out_b= (const float*)d_in[15];
  const float* lno_g  = (const float*)d_in[16], *lno_b  = (const float*)d_in[17];
  const float* o_in_w = (const float*)d_in[18], *o_in_b = (const float*)d_in[19];
  const float* o_out_w= (const float*)d_in[20], *o_out_b= (const float*)d_in[21];
  const float* lnp_g  = (const float*)d_in[22], *lnp_b  = (const float*)d_in[23];
  const float* w1 = (const float*)d_in[24], *b1 = (const float*)d_in[25];
  const float* w2 = (const float*)d_in[26], *b2 = (const float*)d_in[27];
  float* outp = (float*)d_out;

  float *qt, *wkq, *wvo, *y, *den, *t1, *t2, *qkvb, *hid;
  cudaGetSymbolAddress((void**)&qt,   g_qt);
  cudaGetSymbolAddress((void**)&wkq,  g_wkq);
  cudaGetSymbolAddress((void**)&wvo,  g_wvo);
  cudaGetSymbolAddress((void**)&y,    g_y);
  cudaGetSymbolAddress((void**)&den,  g_den);
  cudaGetSymbolAddress((void**)&t1,   g_t1);
  cudaGetSymbolAddress((void**)&t2,   g_t2);
  cudaGetSymbolAddress((void**)&qkvb, g_qkvb);
  cudaGetSymbolAddress((void**)&hid,  g_hid);

  cudaFuncSetAttribute(mega_tail, cudaFuncAttributeMaxDynamicSharedMemorySize, SM_MHA_BYTES);

  // all-resident grid size for the persistent tail (deterministic per device)
  int smCount = 148;
  cudaDeviceGetAttribute(&smCount, cudaDevAttrMultiProcessorCount, 0);
  int maxb = 1;
  cudaOccupancyMaxActiveBlocksPerMultiprocessor(&maxb, mega_tail, 256, SM_MHA_BYTES);
  int nb = maxb * smCount;
  if (nb > 256) nb = 256;
  if (nb < 1) nb = 1;

  const float isq = 0.07216878364870323f;   // 1/sqrt(192)

  // (1) weight pre-products: wkq = wk^T@wq ; wvo = wo@wv
  mm192_dual_kernel<<<dim3(6, 3, 2), 256>>>(wk, wq, wo, wvw, wkq, wvo);
  // (2) qt = isq * LN(prev_slots;lnq) @ wkq^T
  gemm_ln_kernel<<<dim3(32, 3), 256>>>(prev_slots, wkq, nullptr, lnq_g, lnq_b,
                                       qt, DD, isq, 0, 0);
  // (3) fused LN + inverse cross-attention stream (reads features once)
  psb_stream_kernel<<<dim3(BT, NPART), 512>>>(features, qt, lnkv_g, lnkv_b, y, den);
  // (4) persistent tail, all CTAs resident, 8 internal barriers
  mega_tail<<<nb, 256, SM_MHA_BYTES>>>(y, den, wvo, prev_slots,
                                       lnt_g, lnt_b, t_in_w, t_in_b, t_out_w, t_out_b,
                                       lno_g, lno_b, o_in_w, o_in_b, o_out_w, o_out_b,
                                       lnp_g, lnp_b, w1, b1, w2, b2,
                                       t1, t2, qkvb, hid, outp);
}

// round 17
// speedup vs baseline: 1.1545x; 1.0300x over previous
#include <cuda_runtime.h>
#include <cstdint>

#define DD 192
#define LL 1024
#define BT 128
#define NS 8
#define ROWS_S   (BT*NS)   /* 1024 */
#define NPART 4

typedef unsigned long long ull;

// ---------------- scratch (device globals; no allocs allowed) ----------------
__device__ float g_qt  [ROWS_S * DD];
__device__ float g_wkq [DD * DD];
__device__ float g_wvo [DD * DD];
__device__ float g_y   [NPART * ROWS_S * DD];
__device__ float g_den [NPART * ROWS_S];
__device__ float g_t1  [ROWS_S * DD];
__device__ float g_t2  [ROWS_S * DD];
__device__ float g_qkvb[ROWS_S * 576];
__device__ float g_hid [ROWS_S * 512];
__device__ int   g_bar = 0;
__device__ int   g_gen = 0;

// ---------------- packed f32x2 helpers ----------------
__device__ __forceinline__ ull dup2(float x) {
  ull r; asm("mov.b64 %0, {%1, %1};" : "=l"(r) : "f"(x)); return r;
}
__device__ __forceinline__ ull pack2(float lo, float hi) {
  ull r; asm("mov.b64 %0, {%1, %2};" : "=l"(r) : "f"(lo), "f"(hi)); return r;
}
__device__ __forceinline__ void unpack2(ull v, float& lo, float& hi) {
  asm("mov.b64 {%0, %1}, %2;" : "=f"(lo), "=f"(hi) : "l"(v));
}
__device__ __forceinline__ void ffma2(ull& d, ull a, ull b) {
  asm("fma.rn.f32x2 %0, %1, %2, %0;" : "+l"(d) : "l"(a), "l"(b));
}
__device__ __forceinline__ ull add2(ull a, ull b) {
  ull r; asm("add.rn.f32x2 %0, %1, %2;" : "=l"(r) : "l"(a), "l"(b)); return r;
}
__device__ __forceinline__ ull mul2(ull a, ull b) {
  ull r; asm("mul.rn.f32x2 %0, %1, %2;" : "=l"(r) : "l"(a), "l"(b)); return r;
}

// ---------------- grid-wide barrier (all CTAs resident: grid sized by occupancy) ----------------
__device__ __forceinline__ void grid_sync() {
  __syncthreads();
  if (threadIdx.x == 0) {
    volatile int* genp = &g_gen;
    int gen = *genp;
    __threadfence();
    if (atomicAdd(&g_bar, 1) == (int)gridDim.x - 1) {
      g_bar = 0;
      __threadfence();
      *genp = gen + 1;
    } else {
      while (*genp == gen) { }
    }
  }
  __syncthreads();
}

// ---------------- smem layouts (full-K panels; one sync per panel) ----------------
struct SmLn2 { float Af[32][193]; __align__(16) float Wb[DD][68]; float gs[DD], bs[DD]; };   // ~78.5 KB
struct SmGs2 { __align__(16) float As[DD][34]; __align__(16) float Ws[DD][68]; float rs[32]; }; // ~78.5 KB
#define SM_MHA_BYTES ((64*48 + 2*128*48 + 64*128)*4)   /* 94208 */

// ---------------- device fn: fused LN + GEMM tile (K=192), sync-free inner loop ----------------
__device__ void dev_gemm_ln(char* smraw,
                            const float* __restrict__ A, const float* __restrict__ W,
                            const float* __restrict__ bias,
                            const float* __restrict__ gamma, const float* __restrict__ beta,
                            float* __restrict__ C, int ldc, float alpha, int relu, int perm,
                            int tm, int tn) {
  SmLn2* sm = (SmLn2*)smraw;
  int t = threadIdx.x;
  int m0 = tm * 32, n0 = tn * 64;
  // load FULL W panel (64 x 192) while also loading A; k-major layout for compute
  for (int u = t; u < 64*48; u += 256) {
    int r = u / 48, c4 = u - r*48;
    float4 w = *(const float4*)(W + (size_t)(n0 + r)*DD + c4*4);
    sm->Wb[c4*4+0][r] = w.x; sm->Wb[c4*4+1][r] = w.y;
    sm->Wb[c4*4+2][r] = w.z; sm->Wb[c4*4+3][r] = w.w;
  }
  for (int i = t; i < DD; i += 256) { sm->gs[i] = gamma[i]; sm->bs[i] = beta[i]; }
  for (int i = t; i < 32*DD; i += 256) {
    int r = i / DD, c = i - r*DD;
    int sr = m0 + r;
    if (perm) { int w = sr; int bb = w >> 7, n = (w >> 4) & 7, tt = w & 15; sr = (bb*16 + tt)*8 + n; }
    sm->Af[r][c] = A[(size_t)sr*DD + c];
  }
  __syncthreads();
  int wid = t >> 5, lane = t & 31;
#pragma unroll
  for (int i = 0; i < 4; i++) {
    int r = wid*4 + i;
    float s = 0.f, s2 = 0.f;
#pragma unroll
    for (int c0 = 0; c0 < 6; c0++) { float v = sm->Af[r][c0*32 + lane]; s += v; s2 += v*v; }
#pragma unroll
    for (int o = 16; o; o >>= 1) {
      s  += __shfl_xor_sync(0xffffffffu, s,  o);
      s2 += __shfl_xor_sync(0xffffffffu, s2, o);
    }
    float m = s * (1.f/DD);
    float inv = rsqrtf(fmaxf(s2*(1.f/DD) - m*m, 0.f) + 1e-5f);
#pragma unroll
    for (int c0 = 0; c0 < 6; c0++) {
      int c = c0*32 + lane;
      sm->Af[r][c] = (sm->Af[r][c] - m)*inv*sm->gs[c] + sm->bs[c];
    }
  }
  __syncthreads();

  int ty = t >> 4, tx = t & 15;
  ull acc[4] = {};
#pragma unroll 8
  for (int k = 0; k < DD; k++) {
    ull ap = pack2(sm->Af[ty*2][k], sm->Af[ty*2+1][k]);
    float4 w4 = *(const float4*)&sm->Wb[k][tx*4];
    ffma2(acc[0], ap, dup2(w4.x));
    ffma2(acc[1], ap, dup2(w4.y));
    ffma2(acc[2], ap, dup2(w4.z));
    ffma2(acc[3], ap, dup2(w4.w));
  }
  int m = m0 + ty*2, n = n0 + tx*4;
  float r0[4], r1[4];
#pragma unroll
  for (int j = 0; j < 4; j++) {
    float lo, hi; unpack2(acc[j], lo, hi);
    float bv = bias ? bias[n+j] : 0.f;
    float v0 = lo*alpha + bv;
    float v1 = hi*alpha + bv;
    if (relu) { v0 = fmaxf(v0, 0.f); v1 = fmaxf(v1, 0.f); }
    r0[j] = v0; r1[j] = v1;
  }
  *(float4*)(C + (size_t)m*ldc + n)     = make_float4(r0[0], r0[1], r0[2], r0[3]);
  *(float4*)(C + (size_t)(m+1)*ldc + n) = make_float4(r1[0], r1[1], r1[2], r1[3]);
  __syncthreads();
}

// ---------------- device fn: GEMM tile, full-K panel chunks of 192, sync-free inner ----------------
__device__ void dev_gemm_s(char* smraw,
                           const float* __restrict__ A, const float* __restrict__ W,
                           const float* __restrict__ bias, const float* __restrict__ res,
                           const float* __restrict__ rowdiv,
                           float* __restrict__ C, int Ncols, int K, int ldc,
                           float alpha, int relu, int nacc, int tm, int tn) {
  SmGs2* sm = (SmGs2*)smraw;
  int t = threadIdx.x;
  int m0 = tm * 32, n0 = tn * 64;
  if (t < 32) {
    float d = 1.f;
    if (rowdiv) {
      float s = 0.f;
      for (int p = 0; p < nacc; p++) s += rowdiv[p*ROWS_S + m0 + t];
      d = 1.f / s;
    }
    sm->rs[t] = d;
  }
  __syncthreads();
  int ty = t >> 4, tx = t & 15;
  ull acc[4] = {};

  for (int kc0 = 0; kc0 < K; kc0 += DD) {
    int kc = K - kc0; if (kc > DD) kc = DD;
    int nf4 = kc >> 2;
    for (int u = t; u < 32*nf4; u += 256) {
      int r = u / nf4, c4 = u - r*nf4;
      const float* ap = A + (size_t)(m0 + r)*K + kc0 + c4*4;
      float4 a = *(const float4*)ap;
      for (int p = 1; p < nacc; p++) {
        float4 a2 = *(const float4*)(ap + (size_t)p*ROWS_S*DD);
        a.x += a2.x; a.y += a2.y; a.z += a2.z; a.w += a2.w;
      }
      float rv = sm->rs[r];
      a.x *= rv; a.y *= rv; a.z *= rv; a.w *= rv;
      sm->As[c4*4+0][r] = a.x; sm->As[c4*4+1][r] = a.y;
      sm->As[c4*4+2][r] = a.z; sm->As[c4*4+3][r] = a.w;
    }
    for (int u = t; u < 64*nf4; u += 256) {
      int r = u / nf4, c4 = u - r*nf4;
      float4 w = *(const float4*)(W + (size_t)(n0 + r)*K + kc0 + c4*4);
      sm->Ws[c4*4+0][r] = w.x; sm->Ws[c4*4+1][r] = w.y;
      sm->Ws[c4*4+2][r] = w.z; sm->Ws[c4*4+3][r] = w.w;
    }
    __syncthreads();
#pragma unroll 8
    for (int k = 0; k < kc; k++) {
      ull ap = *(const ull*)&sm->As[k][ty*2];
      float4 wv = *(const float4*)&sm->Ws[k][tx*4];
      ffma2(acc[0], ap, dup2(wv.x));
      ffma2(acc[1], ap, dup2(wv.y));
      ffma2(acc[2], ap, dup2(wv.z));
      ffma2(acc[3], ap, dup2(wv.w));
    }
    __syncthreads();
  }

  int m = m0 + ty*2, n = n0 + tx*4;
  float r0[4], r1[4];
#pragma unroll
  for (int j = 0; j < 4; j++) {
    float lo, hi; unpack2(acc[j], lo, hi);
    float bv = bias ? bias[n+j] : 0.f;
    float v0 = lo*alpha + bv;
    float v1 = hi*alpha + bv;
    if (relu) { v0 = fmaxf(v0, 0.f); v1 = fmaxf(v1, 0.f); }
    if (res)  { v0 += res[(size_t)m*Ncols + n+j]; v1 += res[(size_t)(m+1)*Ncols + n+j]; }
    r0[j] = v0; r1[j] = v1;
  }
  *(float4*)(C + (size_t)m*ldc + n)     = make_float4(r0[0], r0[1], r0[2], r0[3]);
  *(float4*)(C + (size_t)(m+1)*ldc + n) = make_float4(r1[0], r1[1], r1[2], r1[3]);
  __syncthreads();
}

// ---------------- device fn: MHA unit (b, h, i0) — R16-proven ----------------
__device__ void dev_mha(char* smraw, const float* __restrict__ qkv, float* __restrict__ out,
                        int S, int Bb, int b, int h, int i0) {
  float* smbuf = (float*)smraw;
  float* qs = smbuf;
  float* ks = qs + 64*48;
  float* vs = ks + S*48;
  float* sc = vs + S*48;
  int t = threadIdx.x;
  for (int i = t; i < 64*48; i += 256) {
    int s = i / 48, e = i - s*48;
    qs[i] = qkv[((size_t)(i0+s)*Bb + b)*576 + h*48 + e];
  }
  for (int i = t; i < S*48; i += 256) {
    int s = i / 48, e = i - s*48;
    size_t ro = ((size_t)s*Bb + b)*576 + h*48 + e;
    ks[i] = qkv[ro + 192]; vs[i] = qkv[ro + 384];
  }
  __syncthreads();
  const float scale = 0.14433756729740643f;
  {
    int iq = t >> 2, s4 = t & 3;
    float4 qreg[12];
#pragma unroll
    for (int j = 0; j < 12; j++) qreg[j] = *(const float4*)(qs + iq*48 + j*4);
    for (int s = s4; s < S; s += 4) {
      const float4* kr = (const float4*)(ks + s*48);
      ull pp = 0;
#pragma unroll
      for (int j = 0; j < 12; j++) {
        float4 kx = kr[j];
        ffma2(pp, pack2(qreg[j].x, qreg[j].y), pack2(kx.x, kx.y));
        ffma2(pp, pack2(qreg[j].z, qreg[j].w), pack2(kx.z, kx.w));
      }
      float lo, hi; unpack2(pp, lo, hi);
      sc[iq*S + s] = (lo + hi) * scale;
    }
  }
  __syncthreads();
  int warp = t >> 5, lane = t & 31;
  for (int i = warp; i < 64; i += 8) {
    float mx = -1e30f;
    for (int s = lane; s < S; s += 32) mx = fmaxf(mx, sc[i*S+s]);
#pragma unroll
    for (int o = 16; o; o >>= 1) mx = fmaxf(mx, __shfl_xor_sync(0xffffffffu, mx, o));
    float sum = 0.f;
    for (int s = lane; s < S; s += 32) { float e = __expf(sc[i*S+s]-mx); sc[i*S+s]=e; sum += e; }
#pragma unroll
    for (int o = 16; o; o >>= 1) sum += __shfl_xor_sync(0xffffffffu, sum, o);
    float r = 1.f / sum;
    for (int s = lane; s < S; s += 32) sc[i*S+s] *= r;
  }
  __syncthreads();
  for (int idx = t; idx < 64*12; idx += 256) {
    int i = idx / 12, e4 = idx - i*12;
    ull a0 = 0, a1 = 0;
    const float* vcol = vs + e4*4;
#pragma unroll 4
    for (int s = 0; s < S; s++) {
      ull w2 = dup2(sc[i*S + s]);
      float4 vv = *(const float4*)(vcol + s*48);
      ffma2(a0, w2, pack2(vv.x, vv.y));
      ffma2(a1, w2, pack2(vv.z, vv.w));
    }
    float o0, o1, o2, o3;
    unpack2(a0, o0, o1); unpack2(a1, o2, o3);
    *(float4*)(out + ((size_t)(i0+i)*Bb + b)*192 + h*48 + e4*4) = make_float4(o0, o1, o2, o3);
  }
  __syncthreads();
}

// ---------------- standalone front kernels ----------------
__global__ __launch_bounds__(256)
void mm192_dual_kernel(const float* __restrict__ wk, const float* __restrict__ wq,
                       const float* __restrict__ wo, const float* __restrict__ wv,
                       float* __restrict__ wkq, float* __restrict__ wvo) {
  int z = blockIdx.z;
  const float* A = z ? wo : wk;
  const float* B = z ? wv : wq;
  float* C = z ? wvo : wkq;
  int transA = z ? 0 : 1;
  __shared__ __align__(16) float As[16][34];
  __shared__ __align__(16) float Ws[16][68];
  int t = threadIdx.x;
  int m0 = blockIdx.x * 32, n0 = blockIdx.y * 64;
  int ty = t >> 4, tx = t & 15;
  ull acc[4] = {};
  int wn = t >> 2, wk2 = (t & 3) << 2;
  for (int k0 = 0; k0 < DD; k0 += 16) {
    float av[2]; int ak[2], am[2];
#pragma unroll
    for (int h = 0; h < 2; h++) {
      int i = t + h*256;
      ak[h] = i >> 5; am[h] = i & 31;
      av[h] = transA ? A[(size_t)(k0 + ak[h])*DD + m0 + am[h]]
                     : A[(size_t)(m0 + am[h])*DD + k0 + ak[h]];
    }
    float wv4[4];
#pragma unroll
    for (int j = 0; j < 4; j++) wv4[j] = B[(size_t)(k0 + wk2 + j)*DD + n0 + wn];
    __syncthreads();
#pragma unroll
    for (int h = 0; h < 2; h++) As[ak[h]][am[h]] = av[h];
#pragma unroll
    for (int j = 0; j < 4; j++) Ws[wk2 + j][wn] = wv4[j];
    __syncthreads();
#pragma unroll
    for (int k = 0; k < 16; k++) {
      ull ap = *(const ull*)&As[k][ty*2];
      float4 w4 = *(const float4*)&Ws[k][tx*4];
      ffma2(acc[0], ap, dup2(w4.x));
      ffma2(acc[1], ap, dup2(w4.y));
      ffma2(acc[2], ap, dup2(w4.z));
      ffma2(acc[3], ap, dup2(w4.w));
    }
  }
  int m = m0 + ty*2, n = n0 + tx*4;
  float r0[4], r1[4];
#pragma unroll
  for (int j = 0; j < 4; j++) unpack2(acc[j], r0[j], r1[j]);
  *(float4*)(C + (size_t)m*DD + n)     = make_float4(r0[0], r0[1], r0[2], r0[3]);
  *(float4*)(C + (size_t)(m+1)*DD + n) = make_float4(r1[0], r1[1], r1[2], r1[3]);
}

__global__ __launch_bounds__(256)
void gemm_ln_kernel(const float* __restrict__ A, const float* __restrict__ W,
                    const float* __restrict__ bias,
                    const float* __restrict__ gamma, const float* __restrict__ beta,
                    float* __restrict__ C, int ldc, float alpha, int relu, int perm) {
  extern __shared__ __align__(16) char smraw[];
  dev_gemm_ln(smraw, A, W, bias, gamma, beta, C, ldc, alpha, relu, perm,
              blockIdx.x, blockIdx.y);
}

// ---------------- psb_stream (R12/R14-proven) ----------------
__global__ __launch_bounds__(512)
void psb_stream_kernel(const float* __restrict__ features, const float* __restrict__ qt,
                       const float* __restrict__ g, const float* __restrict__ b,
                       float* __restrict__ y, float* __restrict__ den) {
  __shared__ ull   qgp[4*DD];
  __shared__ float s1s[NS], bbs[NS];
  __shared__ float ysum[NS*DD];
  __shared__ float csum[NS], dsum[NS];
  int bt = blockIdx.x, q4 = blockIdx.y;
  int t = threadIdx.x, wid = t >> 5, lane = t & 31;
  const float* qtb = qt + (size_t)bt*NS*DD;
  for (int i = t; i < 4*DD; i += 512) {
    int m = i / DD, c = i - m*DD;
    float gc = g[c];
    qgp[m*DD + c] = pack2(gc*qtb[(2*m)*DD + c], gc*qtb[(2*m+1)*DD + c]);
  }
  if (wid < 8) {
    int n = wid;
    float s1 = 0.f, bbv = 0.f;
#pragma unroll
    for (int j = 0; j < 6; j++) {
      int c = j*32 + lane;
      float qv = qtb[n*DD + c];
      s1 += g[c]*qv; bbv += b[c]*qv;
    }
#pragma unroll
    for (int o = 16; o; o >>= 1) {
      s1  += __shfl_xor_sync(0xffffffffu, s1,  o);
      bbv += __shfl_xor_sync(0xffffffffu, bbv, o);
    }
    if (lane == 0) { s1s[n] = s1; bbs[n] = bbv; }
  }
  for (int i = t; i < NS*DD; i += 512) ysum[i] = 0.f;
  if (t < NS) { csum[t] = 0.f; dsum[t] = 0.f; }
  __syncthreads();

  ull s1p[4], bp[4];
#pragma unroll
  for (int m = 0; m < 4; m++) {
    s1p[m] = pack2(s1s[2*m], s1s[2*m+1]);
    bp[m]  = pack2(bbs[2*m], bbs[2*m+1]);
  }
  ull yacc[4][6] = {};
  ull dacc[4] = {};
  ull cacc[4] = {};
  const float* fb = features + (size_t)bt * LL * DD;
  int s_begin = q4*256 + wid;
  int s_end   = q4*256 + 256;
  float vn[6];
  {
    const float* xr = fb + (size_t)s_begin * DD;
#pragma unroll
    for (int j = 0; j < 6; j++) vn[j] = xr[j*32 + lane];
  }
  for (int s = s_begin; s < s_end; s += 16) {
    float v[6];
#pragma unroll
    for (int j = 0; j < 6; j++) v[j] = vn[j];
    int s2i = s + 16;
    if (s2i < s_end) {
      const float* xr = fb + (size_t)s2i * DD;
#pragma unroll
      for (int j = 0; j < 6; j++) vn[j] = xr[j*32 + lane];
    }
    float sm = 0.f, sq = 0.f;
#pragma unroll
    for (int j = 0; j < 6; j++) { sm += v[j]; sq += v[j]*v[j]; }
    ull msq = pack2(sm, sq);
    ull dd[4] = {};
#pragma unroll
    for (int mI = 0; mI < 4; mI++) {
#pragma unroll
      for (int j = 0; j < 6; j++)
        ffma2(dd[mI], dup2(v[j]), qgp[mI*DD + j*32 + lane]);
    }
#pragma unroll
    for (int o = 16; o; o >>= 1) {
      msq = add2(msq, __shfl_xor_sync(0xffffffffu, msq, o));
#pragma unroll
      for (int mI = 0; mI < 4; mI++)
        dd[mI] = add2(dd[mI], __shfl_xor_sync(0xffffffffu, dd[mI], o));
    }
    unpack2(msq, sm, sq);
    float mean = sm * (1.f/DD);
    float inv = rsqrtf(fmaxf(sq*(1.f/DD) - mean*mean, 0.f) + 1e-5f);
    float nim = -inv*mean;
    float p[NS];
#pragma unroll
    for (int mI = 0; mI < 4; mI++) {
      ull pp = bp[mI];
      ffma2(pp, dd[mI], dup2(inv));
      ffma2(pp, s1p[mI], dup2(nim));
      unpack2(pp, p[2*mI], p[2*mI+1]);
    }
    float mx = p[0];
#pragma unroll
    for (int n = 1; n < NS; n++) mx = fmaxf(mx, p[n]);
    float ssum = 0.f;
#pragma unroll
    for (int n = 0; n < NS; n++) { p[n] = __expf(p[n]-mx); ssum += p[n]; }
    float r = 1.f / ssum;
#pragma unroll
    for (int mI = 0; mI < 4; mI++) {
      ull w2 = pack2(p[2*mI]*r, p[2*mI+1]*r);
      dacc[mI] = add2(dacc[mI], w2);
      ull wiv = mul2(w2, dup2(inv));
      ffma2(cacc[mI], wiv, dup2(mean));
#pragma unroll
      for (int j = 0; j < 6; j++) ffma2(yacc[mI][j], dup2(v[j]), wiv);
    }
  }
#pragma unroll
  for (int mI = 0; mI < 4; mI++) {
#pragma unroll
    for (int j = 0; j < 6; j++) {
      float lo, hi; unpack2(yacc[mI][j], lo, hi);
      atomicAdd(&ysum[(2*mI)*DD + j*32 + lane], lo);
      atomicAdd(&ysum[(2*mI+1)*DD + j*32 + lane], hi);
    }
  }
  if (lane == 0) {
#pragma unroll
    for (int mI = 0; mI < 4; mI++) {
      float lo, hi;
      unpack2(dacc[mI], lo, hi);
      atomicAdd(&dsum[2*mI], lo); atomicAdd(&dsum[2*mI+1], hi);
      unpack2(cacc[mI], lo, hi);
      atomicAdd(&csum[2*mI], lo); atomicAdd(&csum[2*mI+1], hi);
    }
  }
  __syncthreads();
  float* yp = y + (size_t)q4 * ROWS_S * DD + (size_t)bt*NS*DD;
  for (int i = t; i < NS*DD; i += 512) {
    int n = i / DD, d = i - n*DD;
    yp[i] = g[d]*(ysum[i] - csum[n]) + b[d]*dsum[n];
  }
  if (t < NS) den[q4*ROWS_S + bt*NS + t] = dsum[t];
}

// ---------------- mega_tail: everything after psb_stream (grid-strided stages) ----------------
__global__ __launch_bounds__(256)
void mega_tail(const float* __restrict__ y, const float* __restrict__ den,
               const float* __restrict__ wvo, const float* __restrict__ prev_slots,
               const float* __restrict__ lnt_g, const float* __restrict__ lnt_b,
               const float* __restrict__ t_in_w, const float* __restrict__ t_in_b,
               const float* __restrict__ t_out_w, const float* __restrict__ t_out_b,
               const float* __restrict__ lno_g, const float* __restrict__ lno_b,
               const float* __restrict__ o_in_w, const float* __restrict__ o_in_b,
               const float* __restrict__ o_out_w, const float* __restrict__ o_out_b,
               const float* __restrict__ lnp_g, const float* __restrict__ lnp_b,
               const float* __restrict__ w1, const float* __restrict__ b1,
               const float* __restrict__ w2, const float* __restrict__ b2,
               float* __restrict__ t1, float* __restrict__ t2,
               float* __restrict__ qkvb, float* __restrict__ hid,
               float* __restrict__ outp) {
  extern __shared__ __align__(16) char smraw[];
  int cta = blockIdx.x, gd = gridDim.x;

  // S1: t1 = (sum_p y_p / sum_p den_p) @ wvo^T  (96 tiles)
  for (int i = cta; i < 96; i += gd)
    dev_gemm_s(smraw, y, wvo, nullptr, nullptr, den, t1, DD, DD, DD, 1.f, 0, NPART, i / 3, i % 3);
  grid_sync();
  // S2: qkvb = LN(t1;lnt) @ t_in_w^T + b  (288 tiles)
  for (int i = cta; i < 288; i += gd)
    dev_gemm_ln(smraw, t1, t_in_w, t_in_b, lnt_g, lnt_b, qkvb, 576, 1.f, 0, 0, i / 9, i % 9);
  grid_sync();
  // S3: time MHA (S=128, Bb=8): 64 units -> t1
  for (int u = cta; u < 64; u += gd) {
    int bh = u & 31, chunk = u >> 5;
    dev_mha(smraw, qkvb, t1, 128, 8, bh >> 2, bh & 3, chunk * 64);
  }
  grid_sync();
  // S4: t2 = t1 @ t_out_w^T + b  (96 tiles)
  for (int i = cta; i < 96; i += gd)
    dev_gemm_s(smraw, t1, t_out_w, t_out_b, nullptr, nullptr, t2, DD, DD, DD, 1.f, 0, 1, i / 3, i % 3);
  grid_sync();
  // S5: qkvb = LN(perm(t2);lno) @ o_in_w^T + b  (288 tiles)
  for (int i = cta; i < 288; i += gd)
    dev_gemm_ln(smraw, t2, o_in_w, o_in_b, lno_g, lno_b, qkvb, 576, 1.f, 0, 1, i / 9, i % 9);
  grid_sync();
  // S6: object MHA (S=64, Bb=16): 64 units -> t1
  for (int u = cta; u < 64; u += gd)
    dev_mha(smraw, qkvb, t1, 64, 16, u >> 2, u & 3, 0);
  grid_sync();
  // S7: t2 = t1 @ o_out_w^T + b  (96 tiles)
  for (int i = cta; i < 96; i += gd)
    dev_gemm_s(smraw, t1, o_out_w, o_out_b, nullptr, nullptr, t2, DD, DD, DD, 1.f, 0, 1, i / 3, i % 3);
  grid_sync();
  // S8: hid = relu(LN(t2;lnp) @ w1^T + b1)  (256 tiles, N=512)
  for (int i = cta; i < 256; i += gd)
    dev_gemm_ln(smraw, t2, w1, b1, lnp_g, lnp_b, hid, 512, 1.f, 1, 0, i / 8, i % 8);
  grid_sync();
  // S9: out = hid @ w2^T + b2 + prev_slots  (96 tiles, K=512)
  for (int i = cta; i < 96; i += gd)
    dev_gemm_s(smraw, hid, w2, b2, prev_slots, nullptr, outp, DD, 512, DD, 1.f, 0, 1, i / 3, i % 3);
}

// ---------------- launcher ----------------
extern "C" void kernel_launch(void* const* d_in, const int* in_sizes, int n_in,
                              void* d_out, int out_size) {
  const float* features   = (const float*)d_in[0];
  const float* prev_slots = (const float*)d_in[1];
  const float* lnq_g  = (const float*)d_in[2],  *lnq_b  = (const float*)d_in[3];
  const float* lnkv_g = (const float*)d_in[4],  *lnkv_b = (const float*)d_in[5];
  const float* wq = (const float*)d_in[6],  *wk = (const float*)d_in[7];
  const float* wvw= (const float*)d_in[8],  *wo = (const float*)d_in[9];
  const float* lnt_g  = (const float*)d_in[10], *lnt_b  = (const float*)d_in[11];
  const float* t_in_w = (const float*)d_in[12], *t_in_b = (const float*)d_in[13];
  const float* t_out_w= (const float*)d_in[14], *t_out_b= (const float*)d_in[15];
  const float* lno_g  = (const float*)d_in[16], *lno_b  = (const float*)d_in[17];
  const float* o_in_w = (const float*)d_in[18], *o_in_b = (const float*)d_in[19];
  const float* o_out_w= (const float*)d_in[20], *o_out_b= (const float*)d_in[21];
  const float* lnp_g  = (const float*)d_in[22], *lnp_b  = (const float*)d_in[23];
  const float* w1 = (const float*)d_in[24], *b1 = (const float*)d_in[25];
  const float* w2 = (const float*)d_in[26], *b2 = (const float*)d_in[27];
  float* outp = (float*)d_out;

  float *qt, *wkq, *wvo, *y, *den, *t1, *t2, *qkvb, *hid;
  cudaGetSymbolAddress((void**)&qt,   g_qt);
  cudaGetSymbolAddress((void**)&wkq,  g_wkq);
  cudaGetSymbolAddress((void**)&wvo,  g_wvo);
  cudaGetSymbolAddress((void**)&y,    g_y);
  cudaGetSymbolAddress((void**)&den,  g_den);
  cudaGetSymbolAddress((void**)&t1,   g_t1);
  cudaGetSymbolAddress((void**)&t2,   g_t2);
  cudaGetSymbolAddress((void**)&qkvb, g_qkvb);
  cudaGetSymbolAddress((void**)&hid,  g_hid);

  cudaFuncSetAttribute(mega_tail, cudaFuncAttributeMaxDynamicSharedMemorySize, SM_MHA_BYTES);
  cudaFuncSetAttribute(gemm_ln_kernel, cudaFuncAttributeMaxDynamicSharedMemorySize, (int)sizeof(SmLn2));

  // all-resident grid size for the persistent tail
  int smCount = 148;
  cudaDeviceGetAttribute(&smCount, cudaDevAttrMultiProcessorCount, 0);
  int maxb = 1;
  cudaOccupancyMaxActiveBlocksPerMultiprocessor(&maxb, mega_tail, 256, SM_MHA_BYTES);
  int nb = maxb * smCount;
  if (nb < 1) nb = 1;
  if (nb > 1024) nb = 1024;

  const float isq = 0.07216878364870323f;   // 1/sqrt(192)

  // (1) weight pre-products: wkq = wk^T@wq ; wvo = wo@wv
  mm192_dual_kernel<<<dim3(6, 3, 2), 256>>>(wk, wq, wo, wvw, wkq, wvo);
  // (2) qt = isq * LN(prev_slots;lnq) @ wkq^T
  gemm_ln_kernel<<<dim3(32, 3), 256, sizeof(SmLn2)>>>(prev_slots, wkq, nullptr, lnq_g, lnq_b,
                                                      qt, DD, isq, 0, 0);
  // (3) fused LN + inverse cross-attention stream (reads features once)
  psb_stream_kernel<<<dim3(BT, NPART), 512>>>(features, qt, lnkv_g, lnkv_b, y, den);
  // (4) persistent tail, all CTAs resident, 8 internal barriers
  mega_tail<<<nb, 256, SM_MHA_BYTES>>>(y, den, wvo, prev_slots,
                                       lnt_g, lnt_b, t_in_w, t_in_b, t_out_w, t_out_b,
                                       lno_g, lno_b, o_in_w, o_in_b, o_out_w, o_out_b,
                                       lnp_g, lnp_b, w1, b1, w2, b2,
                                       t1, t2, qkvb, hid, outp);
}